// round 5
// baseline (speedup 1.0000x reference)
#include <cuda_runtime.h>
#include <cuda_bf16.h>

// Problem constants
#define T_TYPES 27
#define N_NODES 16384
#define B_BATCH 256
#define IN_DIM  300
#define HID     128
#define OUT_DIM 64
#define TILE_B  8                      // batch rows per MLP tile
#define N_TILES (B_BATCH / TILE_B)     // 32

// Scratch: pooled means [T, B, IN_DIM] and per-tile arrival counters.
__device__ __align__(16) float g_pooled[T_TYPES * B_BATCH * IN_DIM];
__device__ int g_ctr[T_TYPES * N_TILES];   // zero-initialized, self-resetting

typedef unsigned long long ull;

__device__ __forceinline__ ull fma2(ull a, ull b, ull c) {
    ull d;
    asm("fma.rn.f32x2 %0, %1, %2, %3;" : "=l"(d) : "l"(a), "l"(b), "l"(c));
    return d;
}
__device__ __forceinline__ ull pack2(float x) {
    ull d; asm("mov.b64 %0, {%1, %1};" : "=l"(d) : "f"(x)); return d;
}
__device__ __forceinline__ void unpack2(ull v, float& lo, float& hi) {
    asm("mov.b64 {%0, %1}, %2;" : "=f"(lo), "=f"(hi) : "l"(v));
}

__device__ __forceinline__ int lower_bound_i32(const int* s, int n, int v) {
    int lo = 0, hi = n;
    while (lo < hi) {
        int mid = (lo + hi) >> 1;
        if (s[mid] < v) lo = mid + 1; else hi = mid;
    }
    return lo;
}

// ---------------------------------------------------------------------------
// Fused kernel: grid=(B,T), 64 threads.
// Phase 1: pool one (t,b) segment (coalesced float4 streaming).
// Phase 2: the LAST block finishing a (t, 8-row) tile runs the 2-layer MLP
//          for that tile inline (f32x2 packed math), writing out[b,t,o].
// ---------------------------------------------------------------------------
__global__ __launch_bounds__(64, 16)
void fused_kernel(const float* __restrict__ feat,
                  const int* __restrict__ seg,
                  const float* __restrict__ W1,
                  const float* __restrict__ b1,
                  const float* __restrict__ W2,
                  const float* __restrict__ b2,
                  float* __restrict__ out) {
    const int b = blockIdx.x;
    const int t = blockIdx.y;
    const int tid = threadIdx.x;

    __shared__ __align__(16) float s_buf[IN_DIM * TILE_B];  // 9600 B (spt, then ht)
    __shared__ int s_bounds[2];
    __shared__ int s_win;

    // ---------------- Phase 1: segment mean pooling ----------------
    const int* s = seg + (size_t)t * N_NODES;
    if (tid < 2) s_bounds[tid] = lower_bound_i32(s, N_NODES, b + tid);
    __syncthreads();

    const int lo = s_bounds[0];
    const int cnt = s_bounds[1] - lo;

    float4 aA = make_float4(0.f, 0.f, 0.f, 0.f);
    float4 aB = make_float4(0.f, 0.f, 0.f, 0.f);
    const bool hasB = tid < 11;   // 300 floats = 75 float4: cols tid and 64+tid

    const float4* fb = (const float4*)(feat + ((size_t)t * N_NODES + lo) * IN_DIM);
    #pragma unroll 4
    for (int r = 0; r < cnt; ++r) {
        float4 v = __ldcs(&fb[tid]);
        aA.x += v.x; aA.y += v.y; aA.z += v.z; aA.w += v.w;
        if (hasB) {
            float4 w = __ldcs(&fb[64 + tid]);
            aB.x += w.x; aB.y += w.y; aB.z += w.z; aB.w += w.w;
        }
        fb += 75;
    }

    const float inv = 1.0f / (float)max(cnt, 1);
    float4* po = (float4*)(g_pooled + ((size_t)t * B_BATCH + b) * IN_DIM);
    po[tid] = make_float4(aA.x * inv, aA.y * inv, aA.z * inv, aA.w * inv);
    if (hasB)
        po[64 + tid] = make_float4(aB.x * inv, aB.y * inv, aB.z * inv, aB.w * inv);

    // ---------------- arrival & winner election ----------------
    __syncthreads();                     // all pooled stores issued
    const int tile = t * N_TILES + (b >> 3);
    if (tid == 0) {
        __threadfence();                 // make pooled row visible device-wide
        int old = atomicAdd(&g_ctr[tile], 1);
        if (old == TILE_B - 1) {
            atomicSub(&g_ctr[tile], TILE_B);   // self-reset for graph replays
            s_win = 1;
        } else {
            s_win = 0;
        }
    }
    __syncthreads();
    if (!s_win) return;
    __threadfence();                     // order subsequent loads after the atomic

    // ---------------- Phase 2: MLP for tile rows [b0, b0+8) ----------------
    const int b0 = (b >> 3) * TILE_B;

    // load pooled tile [8 x 300] transposed into s_buf[k*8 + r] (L2 reads)
    {
        const float* src = g_pooled + ((size_t)t * B_BATCH + b0) * IN_DIM;
        for (int idx = tid; idx < TILE_B * IN_DIM; idx += 64) {
            int r = idx / IN_DIM;
            int k = idx - r * IN_DIM;
            s_buf[k * TILE_B + r] = __ldcg(&src[idx]);
        }
    }
    __syncthreads();

    // GEMM1: h[r][j] = relu(sum_k sp[r][k]*W1[k][j] + b1[j]); two passes, j = tid + 64*pass
    ull hacc[2][4];
    const float* w1base = W1 + (size_t)t * IN_DIM * HID;
    #pragma unroll
    for (int pass = 0; pass < 2; ++pass) {
        const int j = tid + pass * 64;
        ull binit = pack2(b1[t * HID + j]);
        ull a0 = binit, a1 = binit, a2 = binit, a3 = binit;

        const float* w1p = w1base + j;
        float wc[10], wn[10];
        #pragma unroll
        for (int i = 0; i < 10; ++i) wc[i] = w1p[i * HID];

        for (int kg = 0; kg < IN_DIM / 10; ++kg) {
            const int kb = kg * 10;
            if (kg + 1 < IN_DIM / 10) {
                const float* wp2 = w1p + (kb + 10) * HID;
                #pragma unroll
                for (int i = 0; i < 10; ++i) wn[i] = wp2[i * HID];
            }
            #pragma unroll
            for (int q = 0; q < 10; ++q) {
                ull wp = pack2(wc[q]);
                const ulonglong2* sp = (const ulonglong2*)&s_buf[(kb + q) * TILE_B];
                ulonglong2 u0 = sp[0];
                ulonglong2 u1 = sp[1];
                a0 = fma2(wp, u0.x, a0);
                a1 = fma2(wp, u0.y, a1);
                a2 = fma2(wp, u1.x, a2);
                a3 = fma2(wp, u1.y, a3);
            }
            #pragma unroll
            for (int i = 0; i < 10; ++i) wc[i] = wn[i];
        }
        hacc[pass][0] = a0; hacc[pass][1] = a1;
        hacc[pass][2] = a2; hacc[pass][3] = a3;
    }
    __syncthreads();   // everyone done reading spt; reuse s_buf for ht

    // relu + transposed store ht[j*8 + r]
    #pragma unroll
    for (int pass = 0; pass < 2; ++pass) {
        const int j = tid + pass * 64;
        #pragma unroll
        for (int p = 0; p < 4; ++p) {
            float lo2, hi2;
            unpack2(hacc[pass][p], lo2, hi2);
            *(float2*)&s_buf[j * TILE_B + 2 * p] =
                make_float2(fmaxf(lo2, 0.f), fmaxf(hi2, 0.f));
        }
    }
    __syncthreads();

    // GEMM2: out[r][o] = sum_j h[r][j]*W2[j][o] + b2[o]; o = tid
    const int o = tid;
    ull c0, c1, c2, c3;
    {
        ull binit = pack2(b2[t * OUT_DIM + o]);
        c0 = binit; c1 = binit; c2 = binit; c3 = binit;

        const float* w2p = W2 + (size_t)t * HID * OUT_DIM + o;
        float wc[8], wn[8];
        #pragma unroll
        for (int i = 0; i < 8; ++i) wc[i] = w2p[i * OUT_DIM];

        for (int jg = 0; jg < HID / 8; ++jg) {
            const int jb = jg * 8;
            if (jg + 1 < HID / 8) {
                const float* wp2 = w2p + (jb + 8) * OUT_DIM;
                #pragma unroll
                for (int i = 0; i < 8; ++i) wn[i] = wp2[i * OUT_DIM];
            }
            #pragma unroll
            for (int q = 0; q < 8; ++q) {
                ull wp = pack2(wc[q]);
                const ulonglong2* hp = (const ulonglong2*)&s_buf[(jb + q) * TILE_B];
                ulonglong2 u0 = hp[0];
                ulonglong2 u1 = hp[1];
                c0 = fma2(wp, u0.x, c0);
                c1 = fma2(wp, u0.y, c1);
                c2 = fma2(wp, u1.x, c2);
                c3 = fma2(wp, u1.y, c3);
            }
            #pragma unroll
            for (int i = 0; i < 8; ++i) wc[i] = wn[i];
        }
    }

    // out layout: [B, T, OUT]
    {
        float lo2, hi2;
        unpack2(c0, lo2, hi2);
        out[((size_t)(b0 + 0) * T_TYPES + t) * OUT_DIM + o] = lo2;
        out[((size_t)(b0 + 1) * T_TYPES + t) * OUT_DIM + o] = hi2;
        unpack2(c1, lo2, hi2);
        out[((size_t)(b0 + 2) * T_TYPES + t) * OUT_DIM + o] = lo2;
        out[((size_t)(b0 + 3) * T_TYPES + t) * OUT_DIM + o] = hi2;
        unpack2(c2, lo2, hi2);
        out[((size_t)(b0 + 4) * T_TYPES + t) * OUT_DIM + o] = lo2;
        out[((size_t)(b0 + 5) * T_TYPES + t) * OUT_DIM + o] = hi2;
        unpack2(c3, lo2, hi2);
        out[((size_t)(b0 + 6) * T_TYPES + t) * OUT_DIM + o] = lo2;
        out[((size_t)(b0 + 7) * T_TYPES + t) * OUT_DIM + o] = hi2;
    }
}

// ---------------------------------------------------------------------------
extern "C" void kernel_launch(void* const* d_in, const int* in_sizes, int n_in,
                              void* d_out, int out_size) {
    const float* feat = (const float*)d_in[0];
    const int*   seg  = (const int*)d_in[1];
    const float* W1   = (const float*)d_in[2];
    const float* b1   = (const float*)d_in[3];
    const float* W2   = (const float*)d_in[4];
    const float* b2   = (const float*)d_in[5];
    float* out = (float*)d_out;

    dim3 grid(B_BATCH, T_TYPES);
    fused_kernel<<<grid, 64>>>(feat, seg, W1, b1, W2, b2, out);
}

// round 6
// speedup vs baseline: 1.1051x; 1.1051x over previous
#include <cuda_runtime.h>
#include <cuda_bf16.h>

// Problem constants
#define T_TYPES 27
#define N_NODES 16384
#define B_BATCH 256
#define IN_DIM  300
#define HID     128
#define OUT_DIM 64
#define TILE_B  8                      // batch rows per MLP tile
#define N_TILES (B_BATCH / TILE_B)     // 32
#define ROW_F4  75                     // 300 floats = 75 float4

// Scratch: pooled means [T, B, IN_DIM] and per-tile arrival counters.
__device__ __align__(16) float g_pooled[T_TYPES * B_BATCH * IN_DIM];
__device__ int g_ctr[T_TYPES * N_TILES];   // zero-initialized, self-resetting

typedef unsigned long long ull;

__device__ __forceinline__ ull fma2(ull a, ull b, ull c) {
    ull d;
    asm("fma.rn.f32x2 %0, %1, %2, %3;" : "=l"(d) : "l"(a), "l"(b), "l"(c));
    return d;
}
__device__ __forceinline__ ull pack2(float x) {
    ull d; asm("mov.b64 %0, {%1, %1};" : "=l"(d) : "f"(x)); return d;
}
__device__ __forceinline__ void unpack2(ull v, float& lo, float& hi) {
    asm("mov.b64 {%0, %1}, %2;" : "=f"(lo), "=f"(hi) : "l"(v));
}

__device__ __forceinline__ int lower_bound_i32(const int* s, int n, int v) {
    int lo = 0, hi = n;
    while (lo < hi) {
        int mid = (lo + hi) >> 1;
        if (s[mid] < v) lo = mid + 1; else hi = mid;
    }
    return lo;
}

// ---------------------------------------------------------------------------
// Fused kernel: grid=(B,T), 128 threads.
// Phase 1: pool one (t,b) segment. Threads 0..74 own one float4 column each;
//          10-deep explicit load batches maximize outstanding LDGs.
// Phase 2: last block of each (t, 8-row) tile runs the 2-layer MLP inline.
// ---------------------------------------------------------------------------
__global__ __launch_bounds__(128, 8)
void fused_kernel(const float* __restrict__ feat,
                  const int* __restrict__ seg,
                  const float* __restrict__ W1,
                  const float* __restrict__ b1,
                  const float* __restrict__ W2,
                  const float* __restrict__ b2,
                  float* __restrict__ out) {
    const int b = blockIdx.x;
    const int t = blockIdx.y;
    const int tid = threadIdx.x;

    __shared__ __align__(16) float s_buf[IN_DIM * TILE_B];  // 9600 B (spt then ht)
    __shared__ int s_bounds[2];
    __shared__ int s_win;

    // ---------------- Phase 1: segment mean pooling ----------------
    const int* s = seg + (size_t)t * N_NODES;
    if (tid < 2) s_bounds[tid] = lower_bound_i32(s, N_NODES, b + tid);
    __syncthreads();

    const int lo = s_bounds[0];
    const int cnt = s_bounds[1] - lo;

    if (tid < ROW_F4) {
        float4 acc = make_float4(0.f, 0.f, 0.f, 0.f);
        const float4* fb =
            (const float4*)(feat + ((size_t)t * N_NODES + lo) * IN_DIM) + tid;

        int r = 0;
        #pragma unroll 1
        for (; r + 10 <= cnt; r += 10) {
            float4 v[10];
            #pragma unroll
            for (int i = 0; i < 10; ++i) v[i] = __ldcs(fb + i * ROW_F4);
            #pragma unroll
            for (int i = 0; i < 10; ++i) {
                acc.x += v[i].x; acc.y += v[i].y;
                acc.z += v[i].z; acc.w += v[i].w;
            }
            fb += 10 * ROW_F4;
        }
        #pragma unroll 1
        for (; r < cnt; ++r) {
            float4 v = __ldcs(fb);
            acc.x += v.x; acc.y += v.y; acc.z += v.z; acc.w += v.w;
            fb += ROW_F4;
        }

        const float inv = 1.0f / (float)max(cnt, 1);
        float4* po = (float4*)(g_pooled + ((size_t)t * B_BATCH + b) * IN_DIM);
        po[tid] = make_float4(acc.x * inv, acc.y * inv, acc.z * inv, acc.w * inv);
    }

    // ---------------- arrival & winner election ----------------
    __syncthreads();                     // all pooled stores issued
    const int tile = t * N_TILES + (b >> 3);
    if (tid == 0) {
        __threadfence();                 // make pooled row visible device-wide
        int old = atomicAdd(&g_ctr[tile], 1);
        if (old == TILE_B - 1) {
            atomicSub(&g_ctr[tile], TILE_B);   // self-reset for graph replays
            s_win = 1;
        } else {
            s_win = 0;
        }
    }
    __syncthreads();
    if (!s_win) return;
    __threadfence();                     // order subsequent loads after the atomic

    // ---------------- Phase 2: MLP for tile rows [b0, b0+8) ----------------
    const int b0 = (b >> 3) * TILE_B;

    // load pooled tile [8 x 300] transposed into s_buf[k*8 + r]
    {
        const float* src = g_pooled + ((size_t)t * B_BATCH + b0) * IN_DIM;
        for (int idx = tid; idx < TILE_B * IN_DIM; idx += 128) {
            int r = idx / IN_DIM;
            int k = idx - r * IN_DIM;
            s_buf[k * TILE_B + r] = __ldcg(&src[idx]);
        }
    }
    __syncthreads();

    // GEMM1: h[r][j] = relu(sum_k sp[r][k]*W1[k][j] + b1[j]); j = tid (0..127)
    const int j = tid;
    ull hacc[4];
    {
        ull binit = pack2(b1[t * HID + j]);
        #pragma unroll
        for (int p = 0; p < 4; ++p) hacc[p] = binit;

        const float* w1p = W1 + (size_t)t * IN_DIM * HID + j;
        float wc[10], wn[10];
        #pragma unroll
        for (int i = 0; i < 10; ++i) wc[i] = w1p[i * HID];

        for (int kg = 0; kg < IN_DIM / 10; ++kg) {
            const int kb = kg * 10;
            if (kg + 1 < IN_DIM / 10) {
                const float* wp2 = w1p + (kb + 10) * HID;
                #pragma unroll
                for (int i = 0; i < 10; ++i) wn[i] = wp2[i * HID];
            }
            #pragma unroll
            for (int q = 0; q < 10; ++q) {
                ull wp = pack2(wc[q]);
                const ulonglong2* sp = (const ulonglong2*)&s_buf[(kb + q) * TILE_B];
                ulonglong2 u0 = sp[0];
                ulonglong2 u1 = sp[1];
                hacc[0] = fma2(wp, u0.x, hacc[0]);
                hacc[1] = fma2(wp, u0.y, hacc[1]);
                hacc[2] = fma2(wp, u1.x, hacc[2]);
                hacc[3] = fma2(wp, u1.y, hacc[3]);
            }
            #pragma unroll
            for (int i = 0; i < 10; ++i) wc[i] = wn[i];
        }
    }
    __syncthreads();   // done reading spt; reuse s_buf for ht

    // relu + transposed store ht[j*8 + r]
    #pragma unroll
    for (int p = 0; p < 4; ++p) {
        float lo2, hi2;
        unpack2(hacc[p], lo2, hi2);
        *(float2*)&s_buf[j * TILE_B + 2 * p] =
            make_float2(fmaxf(lo2, 0.f), fmaxf(hi2, 0.f));
    }
    __syncthreads();

    // GEMM2: out[r][o] = sum_j h[r][j]*W2[j][o] + b2[o]
    const int o  = tid & 63;
    const int rh = tid >> 6;              // rows rh*4 .. rh*4+3 (2 pairs)
    ull c0, c1;
    {
        ull binit = pack2(b2[t * OUT_DIM + o]);
        c0 = binit; c1 = binit;

        const float* w2p = W2 + (size_t)t * HID * OUT_DIM + o;
        float wc[16], wn[16];
        #pragma unroll
        for (int i = 0; i < 16; ++i) wc[i] = w2p[i * OUT_DIM];

        for (int jg = 0; jg < HID / 16; ++jg) {
            const int jb = jg * 16;
            if (jg + 1 < HID / 16) {
                const float* wp2 = w2p + (jb + 16) * OUT_DIM;
                #pragma unroll
                for (int i = 0; i < 16; ++i) wn[i] = wp2[i * OUT_DIM];
            }
            #pragma unroll
            for (int q = 0; q < 16; ++q) {
                ull wp = pack2(wc[q]);
                ulonglong2 u =
                    *(const ulonglong2*)&s_buf[(jb + q) * TILE_B + rh * 4];
                c0 = fma2(wp, u.x, c0);
                c1 = fma2(wp, u.y, c1);
            }
            #pragma unroll
            for (int i = 0; i < 16; ++i) wc[i] = wn[i];
        }
    }

    // out layout: [B, T, OUT]
    {
        float lo2, hi2;
        unpack2(c0, lo2, hi2);
        out[((size_t)(b0 + rh * 4 + 0) * T_TYPES + t) * OUT_DIM + o] = lo2;
        out[((size_t)(b0 + rh * 4 + 1) * T_TYPES + t) * OUT_DIM + o] = hi2;
        unpack2(c1, lo2, hi2);
        out[((size_t)(b0 + rh * 4 + 2) * T_TYPES + t) * OUT_DIM + o] = lo2;
        out[((size_t)(b0 + rh * 4 + 3) * T_TYPES + t) * OUT_DIM + o] = hi2;
    }
}

// ---------------------------------------------------------------------------
extern "C" void kernel_launch(void* const* d_in, const int* in_sizes, int n_in,
                              void* d_out, int out_size) {
    const float* feat = (const float*)d_in[0];
    const int*   seg  = (const int*)d_in[1];
    const float* W1   = (const float*)d_in[2];
    const float* b1   = (const float*)d_in[3];
    const float* W2   = (const float*)d_in[4];
    const float* b2   = (const float*)d_in[5];
    float* out = (float*)d_out;

    dim3 grid(B_BATCH, T_TYPES);
    fused_kernel<<<grid, 128>>>(feat, seg, W1, b1, W2, b2, out);
}

// round 8
// speedup vs baseline: 1.1662x; 1.0553x over previous
#include <cuda_runtime.h>
#include <cuda_bf16.h>

// Problem constants
#define T_TYPES 27
#define N_NODES 16384
#define B_BATCH 256
#define IN_DIM  300
#define HID     128
#define OUT_DIM 64
#define TILE_B  8
#define N_TILES (B_BATCH / TILE_B)     // 32
#define ROW_F4  75                     // 300 floats = 75 float4

// Scratch
__device__ __align__(16) float g_pooled[T_TYPES * B_BATCH * IN_DIM];
__device__ int g_ctr[T_TYPES * N_TILES];       // zero-init, self-resetting
__device__ int g_bounds[T_TYPES * (B_BATCH + 1)];

typedef unsigned long long ull;

__device__ __forceinline__ ull fma2(ull a, ull b, ull c) {
    ull d;
    asm("fma.rn.f32x2 %0, %1, %2, %3;" : "=l"(d) : "l"(a), "l"(b), "l"(c));
    return d;
}
__device__ __forceinline__ ull pack2(float x) {
    ull d; asm("mov.b64 %0, {%1, %1};" : "=l"(d) : "f"(x)); return d;
}
__device__ __forceinline__ void unpack2(ull v, float& lo, float& hi) {
    asm("mov.b64 {%0, %1}, %2;" : "=f"(lo), "=f"(hi) : "l"(v));
}

__device__ __forceinline__ int lower_bound_i32(const int* s, int n, int v) {
    int lo = 0, hi = n;
    while (lo < hi) {
        int mid = (lo + hi) >> 1;
        if (s[mid] < v) lo = mid + 1; else hi = mid;
    }
    return lo;
}

// ---------------------------------------------------------------------------
// Kernel 0: precompute segment bounds. grid=27, block=256.
// ---------------------------------------------------------------------------
__global__ void bounds_kernel(const int* __restrict__ seg) {
    const int t = blockIdx.x;
    const int b = threadIdx.x;
    const int* s = seg + (size_t)t * N_NODES;
    g_bounds[t * (B_BATCH + 1) + b] = lower_bound_i32(s, N_NODES, b);
    if (b == 0) g_bounds[t * (B_BATCH + 1) + B_BATCH] = N_NODES;
}

// ---------------------------------------------------------------------------
// Fused kernel: grid=(B,T), 128 threads.
// Phase 1: all 4 warps stream rows of one (t,b) segment (row-parallel),
//          partial sums combined via smem.
// Phase 2: last block of each (t, 8-row) tile runs the 2-layer MLP inline.
// ---------------------------------------------------------------------------
__global__ __launch_bounds__(128, 8)
void fused_kernel(const float* __restrict__ feat,
                  const float* __restrict__ W1,
                  const float* __restrict__ b1,
                  const float* __restrict__ W2,
                  const float* __restrict__ b2,
                  float* __restrict__ out) {
    const int b = blockIdx.x;
    const int t = blockIdx.y;
    const int tid = threadIdx.x;
    const int lane = tid & 31;
    const int w = tid >> 5;

    __shared__ __align__(16) float s_buf[IN_DIM * TILE_B];  // 9600 B (red/spt/ht)
    __shared__ int s_win;

    // ---------------- Phase 1: segment mean pooling ----------------
    const int lo  = g_bounds[t * (B_BATCH + 1) + b];
    const int cnt = g_bounds[t * (B_BATCH + 1) + b + 1] - lo;

    const bool has2 = lane < (ROW_F4 - 64);   // lane < 11
    float4 a0 = make_float4(0.f, 0.f, 0.f, 0.f);
    float4 a1 = a0, a2 = a0;
    const float4 z4 = a0;

    {
        const float4* base =
            (const float4*)(feat + ((size_t)t * N_NODES + lo) * IN_DIM);
        int r = w;
        #pragma unroll 1
        for (; r + 4 < cnt; r += 8) {
            const float4* p0 = base + (size_t)r * ROW_F4;
            const float4* p1 = p0 + 4 * ROW_F4;
            float4 v0 = __ldcs(p0 + lane);
            float4 v1 = __ldcs(p0 + 32 + lane);
            float4 v2 = has2 ? __ldcs(p0 + 64 + lane) : z4;
            float4 u0 = __ldcs(p1 + lane);
            float4 u1 = __ldcs(p1 + 32 + lane);
            float4 u2 = has2 ? __ldcs(p1 + 64 + lane) : z4;
            a0.x += v0.x; a0.y += v0.y; a0.z += v0.z; a0.w += v0.w;
            a1.x += v1.x; a1.y += v1.y; a1.z += v1.z; a1.w += v1.w;
            a2.x += v2.x; a2.y += v2.y; a2.z += v2.z; a2.w += v2.w;
            a0.x += u0.x; a0.y += u0.y; a0.z += u0.z; a0.w += u0.w;
            a1.x += u1.x; a1.y += u1.y; a1.z += u1.z; a1.w += u1.w;
            a2.x += u2.x; a2.y += u2.y; a2.z += u2.z; a2.w += u2.w;
        }
        if (r < cnt) {
            const float4* p0 = base + (size_t)r * ROW_F4;
            float4 v0 = __ldcs(p0 + lane);
            float4 v1 = __ldcs(p0 + 32 + lane);
            float4 v2 = has2 ? __ldcs(p0 + 64 + lane) : z4;
            a0.x += v0.x; a0.y += v0.y; a0.z += v0.z; a0.w += v0.w;
            a1.x += v1.x; a1.y += v1.y; a1.z += v1.z; a1.w += v1.w;
            a2.x += v2.x; a2.y += v2.y; a2.z += v2.z; a2.w += v2.w;
        }
    }

    // cross-warp reduction via smem: red[w][col] (4 x 75 float4 = 4800 B)
    {
        float4* red = (float4*)s_buf;
        red[w * ROW_F4 + lane]      = a0;
        red[w * ROW_F4 + 32 + lane] = a1;
        if (has2) red[w * ROW_F4 + 64 + lane] = a2;
    }
    __syncthreads();

    if (tid < ROW_F4) {
        const float4* red = (const float4*)s_buf;
        float4 s0 = red[tid];
        float4 s1 = red[ROW_F4 + tid];
        float4 s2 = red[2 * ROW_F4 + tid];
        float4 s3 = red[3 * ROW_F4 + tid];
        const float inv = 1.0f / (float)max(cnt, 1);
        float4 m = make_float4((s0.x + s1.x + s2.x + s3.x) * inv,
                               (s0.y + s1.y + s2.y + s3.y) * inv,
                               (s0.z + s1.z + s2.z + s3.z) * inv,
                               (s0.w + s1.w + s2.w + s3.w) * inv);
        float4* po = (float4*)(g_pooled + ((size_t)t * B_BATCH + b) * IN_DIM);
        po[tid] = m;
    }

    // ---------------- arrival & winner election ----------------
    __threadfence();                     // order each thread's pooled stores
    __syncthreads();
    const int tile = t * N_TILES + (b >> 3);
    if (tid == 0) {
        int old = atomicAdd(&g_ctr[tile], 1);
        if (old == TILE_B - 1) {
            atomicSub(&g_ctr[tile], TILE_B);   // self-reset for graph replays
            s_win = 1;
        } else {
            s_win = 0;
        }
    }
    __syncthreads();
    if (!s_win) return;
    __threadfence();                     // acquire before reading peers' rows

    // ---------------- Phase 2: MLP for tile rows [b0, b0+8) ----------------
    const int b0 = (b >> 3) * TILE_B;

    // load pooled tile [8 x 300] transposed into s_buf[k*8 + r]
    {
        const float* src = g_pooled + ((size_t)t * B_BATCH + b0) * IN_DIM;
        for (int idx = tid; idx < TILE_B * IN_DIM; idx += 128) {
            int r = idx / IN_DIM;
            int k = idx - r * IN_DIM;
            s_buf[k * TILE_B + r] = __ldcg(&src[idx]);
        }
    }
    __syncthreads();

    // GEMM1: h[r][j] = relu(sum_k sp[r][k]*W1[k][j] + b1[j]); j = tid
    const int j = tid;
    ull hacc[4];
    {
        ull binit = pack2(b1[t * HID + j]);
        #pragma unroll
        for (int p = 0; p < 4; ++p) hacc[p] = binit;

        const float* w1p = W1 + (size_t)t * IN_DIM * HID + j;
        float wc[10], wn[10];
        #pragma unroll
        for (int i = 0; i < 10; ++i) wc[i] = w1p[i * HID];

        for (int kg = 0; kg < IN_DIM / 10; ++kg) {
            const int kb = kg * 10;
            if (kg + 1 < IN_DIM / 10) {
                const float* wp2 = w1p + (kb + 10) * HID;
                #pragma unroll
                for (int i = 0; i < 10; ++i) wn[i] = wp2[i * HID];
            }
            #pragma unroll
            for (int q = 0; q < 10; ++q) {
                ull wp = pack2(wc[q]);
                const ulonglong2* sp = (const ulonglong2*)&s_buf[(kb + q) * TILE_B];
                ulonglong2 u0 = sp[0];
                ulonglong2 u1 = sp[1];
                hacc[0] = fma2(wp, u0.x, hacc[0]);
                hacc[1] = fma2(wp, u0.y, hacc[1]);
                hacc[2] = fma2(wp, u1.x, hacc[2]);
                hacc[3] = fma2(wp, u1.y, hacc[3]);
            }
            #pragma unroll
            for (int i = 0; i < 10; ++i) wc[i] = wn[i];
        }
    }
    __syncthreads();   // done reading spt; reuse s_buf for ht

    // relu + transposed store ht[j*8 + r]
    #pragma unroll
    for (int p = 0; p < 4; ++p) {
        float lo2, hi2;
        unpack2(hacc[p], lo2, hi2);
        *(float2*)&s_buf[j * TILE_B + 2 * p] =
            make_float2(fmaxf(lo2, 0.f), fmaxf(hi2, 0.f));
    }
    __syncthreads();

    // GEMM2: out[r][o] = sum_j h[r][j]*W2[j][o] + b2[o]
    const int o  = tid & 63;
    const int rh = tid >> 6;              // rows rh*4 .. rh*4+3 (2 pairs)
    ull c0, c1;
    {
        ull binit = pack2(b2[t * OUT_DIM + o]);
        c0 = binit; c1 = binit;

        const float* w2p = W2 + (size_t)t * HID * OUT_DIM + o;
        float wc[16], wn[16];
        #pragma unroll
        for (int i = 0; i < 16; ++i) wc[i] = w2p[i * OUT_DIM];

        for (int jg = 0; jg < HID / 16; ++jg) {
            const int jb = jg * 16;
            if (jg + 1 < HID / 16) {
                const float* wp2 = w2p + (jb + 16) * OUT_DIM;
                #pragma unroll
                for (int i = 0; i < 16; ++i) wn[i] = wp2[i * OUT_DIM];
            }
            #pragma unroll
            for (int q = 0; q < 16; ++q) {
                ull wp = pack2(wc[q]);
                ulonglong2 u =
                    *(const ulonglong2*)&s_buf[(jb + q) * TILE_B + rh * 4];
                c0 = fma2(wp, u.x, c0);
                c1 = fma2(wp, u.y, c1);
            }
            #pragma unroll
            for (int i = 0; i < 16; ++i) wc[i] = wn[i];
        }
    }

    // out layout: [B, T, OUT]
    {
        float lo2, hi2;
        unpack2(c0, lo2, hi2);
        out[((size_t)(b0 + rh * 4 + 0) * T_TYPES + t) * OUT_DIM + o] = lo2;
        out[((size_t)(b0 + rh * 4 + 1) * T_TYPES + t) * OUT_DIM + o] = hi2;
        unpack2(c1, lo2, hi2);
        out[((size_t)(b0 + rh * 4 + 2) * T_TYPES + t) * OUT_DIM + o] = lo2;
        out[((size_t)(b0 + rh * 4 + 3) * T_TYPES + t) * OUT_DIM + o] = hi2;
    }
}

// ---------------------------------------------------------------------------
extern "C" void kernel_launch(void* const* d_in, const int* in_sizes, int n_in,
                              void* d_out, int out_size) {
    const float* feat = (const float*)d_in[0];
    const int*   seg  = (const int*)d_in[1];
    const float* W1   = (const float*)d_in[2];
    const float* b1   = (const float*)d_in[3];
    const float* W2   = (const float*)d_in[4];
    const float* b2   = (const float*)d_in[5];
    float* out = (float*)d_out;

    bounds_kernel<<<T_TYPES, B_BATCH>>>(seg);

    dim3 grid(B_BATCH, T_TYPES);
    fused_kernel<<<grid, 128>>>(feat, W1, b1, W2, b2, out);
}